// round 9
// baseline (speedup 1.0000x reference)
#include <cuda_runtime.h>
#include <cuda_bf16.h>
#include <math.h>

// Problem shape (fixed by the dataset): x = [4, 32, 4096, 128] fp32.
#define SEQ     4096
#define HDIM    128
#define HALF    (HDIM / 2)          // 64 rotation pairs per row
#define F4_ROW  (HDIM / 4)          // 32 float4 per row (2 pairs per float4)
#define BH      (4 * 32)            // 128 batch*head slices
#define SLICE   (SEQ * F4_ROW)      // float4 per bh-slice = 131072
#define SPLIT   4                   // bh-loop split -> 4x threads, more MLP
#define BH_PER  (BH / SPLIT)        // 32 bh iterations per thread

// ---------------------------------------------------------------------------
// Position loader with dtype sniffing (reference says int64; harness may have
// materialized int32/float32). Positions are small non-negative ints.
// ---------------------------------------------------------------------------
__device__ __forceinline__ double load_pos(const void* p, int s) {
    const unsigned int* w = (const unsigned int*)p;
    bool hi_zero = (w[1] == 0u) & (w[3] == 0u) & (w[5] == 0u) & (w[7] == 0u);
    bool lo_some = (w[0] | w[2] | w[4] | w[6]) != 0u;
    if (hi_zero && (lo_some || (w[8] | w[9]) == 0u)) {
        return (double)((const long long*)p)[s];
    }
    bool small_ints = (w[1] < (1u << 24)) & (w[2] < (1u << 24)) &
                      (w[3] < (1u << 24));
    if (small_ints) return (double)((const int*)p)[s];
    return (double)((const float*)p)[s];
}

__device__ __forceinline__ float reduce_2pi(double a) {
    const double INV_2PI = 0.15915494309189535;
    const double TWO_PI  = 6.283185307179586;
    double k = rint(a * INV_2PI);
    return (float)(a - k * TWO_PI);
}

// ---------------------------------------------------------------------------
// Fused kernel. 64 threads/block build the 64 inv_freq values (accurate
// double exp2) into shared memory once; every thread then needs only 2 FP64
// muls + rint for its angles. Memory loop is the measured-good R3 pattern:
// __ldg + plain store, unroll 8, one float4 column per thread, BH_PER slices.
// ---------------------------------------------------------------------------
__global__ __launch_bounds__(256) void rope_fused(
    const float4* __restrict__ x, float4* __restrict__ out,
    const void* __restrict__ pos) {
    __shared__ double sfreq[2 * F4_ROW];   // 64 inv_freq values

    int tid = threadIdx.x;
    if (tid < 2 * F4_ROW) {
        const double LOG2_THETA = 13.287712379549449;   // log2(10000)
        sfreq[tid] = exp2(-((double)tid / (double)HALF) * LOG2_THETA);
    }

    int t = blockIdx.x * blockDim.x + tid;   // 0..SLICE-1
    int s = t >> 5;          // seq index
    int j = t & 31;          // float4 within row -> pairs 2j, 2j+1
    double p = load_pos(pos, s);             // independent of smem fill

    __syncthreads();

    float a0 = reduce_2pi(p * sfreq[2 * j]);
    float a1 = reduce_2pi(p * sfreq[2 * j + 1]);
    float s0, c0, s1, c1;
    sincosf(a0, &s0, &c0);
    sincosf(a1, &s1, &c1);

    size_t off = (size_t)blockIdx.y * (size_t)BH_PER * SLICE + (size_t)t;
#pragma unroll 8
    for (int b = 0; b < BH_PER; ++b, off += SLICE) {
        float4 v = __ldg(&x[off]);
        float4 r;
        r.x = c0 * v.x - s0 * v.y;
        r.y = s0 * v.x + c0 * v.y;
        r.z = c1 * v.z - s1 * v.w;
        r.w = s1 * v.z + c1 * v.w;
        out[off] = r;
    }
}

// ---------------------------------------------------------------------------
// Entry point. Identify x vs token_positions by element count (robust to
// input ordering): x has 67108864 elements, positions 4096.
// ---------------------------------------------------------------------------
extern "C" void kernel_launch(void* const* d_in, const int* in_sizes, int n_in,
                              void* d_out, int out_size) {
    const void* xp = d_in[0];
    const void* pp = (n_in > 1) ? d_in[1] : d_in[0];
    if (n_in > 1 && in_sizes[0] < in_sizes[1]) {
        xp = d_in[1];
        pp = d_in[0];
    }
    const float4* x = (const float4*)xp;
    float4* out = (float4*)d_out;

    dim3 grid(SLICE / 256, SPLIT);
    rope_fused<<<grid, 256>>>(x, out, pp);
}

// round 10
// speedup vs baseline: 1.0225x; 1.0225x over previous
#include <cuda_runtime.h>
#include <cuda_bf16.h>
#include <math.h>

// Problem shape (fixed by the dataset): x = [4, 32, 4096, 128] fp32.
#define SEQ     4096
#define HDIM    128
#define HALF    (HDIM / 2)          // 64 rotation pairs per row
#define F4_ROW  (HDIM / 4)          // 32 float4 per row (2 pairs per float4)
#define BH      (4 * 32)            // 128 batch*head slices
#define SLICE   (SEQ * F4_ROW)      // float4 per bh-slice = 131072

// ---------------------------------------------------------------------------
// Position loader with dtype sniffing (reference says int64; harness may have
// materialized int32/float32). Positions are small non-negative ints.
// ---------------------------------------------------------------------------
__device__ __forceinline__ double load_pos(const void* p, int s) {
    const unsigned int* w = (const unsigned int*)p;
    bool hi_zero = (w[1] == 0u) & (w[3] == 0u) & (w[5] == 0u) & (w[7] == 0u);
    bool lo_some = (w[0] | w[2] | w[4] | w[6]) != 0u;
    if (hi_zero && (lo_some || (w[8] | w[9]) == 0u)) {
        return (double)((const long long*)p)[s];
    }
    bool small_ints = (w[1] < (1u << 24)) & (w[2] < (1u << 24)) &
                      (w[3] < (1u << 24));
    if (small_ints) return (double)((const int*)p)[s];
    return (double)((const float*)p)[s];
}

__device__ __forceinline__ float reduce_2pi(double a) {
    const double INV_2PI = 0.15915494309189535;
    const double TWO_PI  = 6.283185307179586;
    double k = rint(a * INV_2PI);
    return (float)(a - k * TWO_PI);
}

// ---------------------------------------------------------------------------
// Fused single-launch kernel, memory shape identical to the measured-best R3
// rope_apply (grid=512x1, 256 thr, one float4 column per thread, BH=128 loop,
// __ldg + plain store, unroll 8 -> DRAM 77.6%). Trig: 64 threads/block build
// the 64 inv_freq values (accurate double exp2) into smem; each thread then
// needs 2 FP64 muls + rint + fp32 sincos, once, amortized over 128 slices.
// ---------------------------------------------------------------------------
__global__ __launch_bounds__(256) void rope_fused(
    const float4* __restrict__ x, float4* __restrict__ out,
    const void* __restrict__ pos) {
    __shared__ double sfreq[2 * F4_ROW];   // 64 inv_freq values

    int tid = threadIdx.x;
    if (tid < 2 * F4_ROW) {
        const double LOG2_THETA = 13.287712379549449;   // log2(10000)
        sfreq[tid] = exp2(-((double)tid / (double)HALF) * LOG2_THETA);
    }

    int t = blockIdx.x * blockDim.x + tid;   // 0..SLICE-1
    int s = t >> 5;          // seq index
    int j = t & 31;          // float4 within row -> pairs 2j, 2j+1
    double p = load_pos(pos, s);             // independent of smem fill

    __syncthreads();

    float a0 = reduce_2pi(p * sfreq[2 * j]);
    float a1 = reduce_2pi(p * sfreq[2 * j + 1]);
    float s0, c0, s1, c1;
    sincosf(a0, &s0, &c0);
    sincosf(a1, &s1, &c1);

    size_t off = (size_t)t;
#pragma unroll 8
    for (int b = 0; b < BH; ++b, off += SLICE) {
        float4 v = __ldg(&x[off]);
        float4 r;
        r.x = c0 * v.x - s0 * v.y;
        r.y = s0 * v.x + c0 * v.y;
        r.z = c1 * v.z - s1 * v.w;
        r.w = s1 * v.z + c1 * v.w;
        out[off] = r;
    }
}

// ---------------------------------------------------------------------------
// Entry point. Identify x vs token_positions by element count (robust to
// input ordering): x has 67108864 elements, positions 4096.
// ---------------------------------------------------------------------------
extern "C" void kernel_launch(void* const* d_in, const int* in_sizes, int n_in,
                              void* d_out, int out_size) {
    const void* xp = d_in[0];
    const void* pp = (n_in > 1) ? d_in[1] : d_in[0];
    if (n_in > 1 && in_sizes[0] < in_sizes[1]) {
        xp = d_in[1];
        pp = d_in[0];
    }
    const float4* x = (const float4*)xp;
    float4* out = (float4*)d_out;

    rope_fused<<<SLICE / 256, 256>>>(x, out, pp);
}